// round 15
// baseline (speedup 1.0000x reference)
#include <cuda_runtime.h>
#include <cuda_bf16.h>
#include <math.h>

#define T_STEPS 300
#define DIN 39
#define H1D 35
#define H2D 30
#define BT 64
#define BATCH 4096
#define NBLK (BATCH/BT)
#define NT 800           // 12 L1 warps + 12 L2 warps + 1 stager

#define RS 160           // u16 per packed row (5 kc * 32)
#define N1 144           // L1 gate cols (36 units * 4)
#define N2 128           // L2 gate cols (32 units * 4)

// smem byte offsets (16B aligned)
#define B1_OFF   0
#define B2_OFF   576
#define W1_OFF   1088                     // 144*160*2 = 46080
#define W2_OFF   47168                    // 128*160*2 = 40960
#define A1_OFF   88128                    // 2 buf * 64*160*2 = 40960
#define A2_OFF   129088                   // 40960
#define SMEM_BYTES 170048
#define ABUF (64*RS)       // u16 elements per A buffer (10240)

typedef unsigned long long ull;
typedef unsigned short u16;
typedef unsigned int u32;

// scratch: LSTM hidden states [T][60][B]  (fw units [0,30), bw [30,60))
__device__ float g_hbuf[(size_t)BATCH * T_STEPS * 60];
// packed x: [T][btile][64 rows][80 u16 dense]  (kc0,kc1 full + kc2 grp0 slots)
__device__ u16 g_xp[(size_t)T_STEPS * NBLK * 64 * 80];

// ---------------- helpers ----------------
__device__ __forceinline__ ull fma2(ull a, ull b, ull c) {
    ull d;
    asm("fma.rn.f32x2 %0, %1, %2, %3;" : "=l"(d) : "l"(a), "l"(b), "l"(c));
    return d;
}
__device__ __forceinline__ ull pack2(float lo, float hi) {
    ull d;
    asm("mov.b64 %0, {%1, %2};" : "=l"(d) : "f"(lo), "f"(hi));
    return d;
}
__device__ __forceinline__ void unpack2(ull v, float& lo, float& hi) {
    asm("mov.b64 {%0, %1}, %2;" : "=f"(lo), "=f"(hi) : "l"(v));
}
__device__ __forceinline__ float sigf(float x) {
    return __fdividef(1.0f, 1.0f + __expf(-x));
}
__device__ __forceinline__ float tanhfast(float x) {
    return 2.0f * sigf(2.0f * x) - 1.0f;
}
__device__ __forceinline__ float cellone(float zi, float zj, float zf, float zo, float& c) {
    c = sigf(zf + 1.0f) * c + sigf(zi) * tanhfast(zj);
    return sigf(zo) * tanhfast(c);
}
__device__ __forceinline__ void bsplit(float v, u16& hi, u16& lo) {
    __nv_bfloat16 h = __float2bfloat16(v);
    float r = v - __bfloat162float(h);
    __nv_bfloat16 l = __float2bfloat16(r);
    hi = __bfloat16_as_ushort(h);
    lo = __bfloat16_as_ushort(l);
}

// packed-row offset for (k, half): bijection (k,half) -> 0..159
__device__ __forceinline__ int pk_off(int k, int half) {
    int kc = k >> 4, rem = k & 15, pair = rem >> 1, odd = k & 1;
    int tq = pair & 3, grp = pair >> 2;
    return kc*32 + tq*8 + grp*4 + half*2 + odd;
}

__device__ __forceinline__ void mma16816(float& c0, float& c1, float& c2, float& c3,
                                         u32 a0, u32 a1, u32 a2, u32 a3,
                                         u32 b0, u32 b1)
{
    asm volatile("mma.sync.aligned.m16n8k16.row.col.f32.bf16.bf16.f32 "
                 "{%0,%1,%2,%3},{%4,%5,%6,%7},{%8,%9},{%0,%1,%2,%3};"
                 : "+f"(c0), "+f"(c1), "+f"(c2), "+f"(c3)
                 : "r"(a0), "r"(a1), "r"(a2), "r"(a3), "r"(b0), "r"(b1));
}

// Fused MMA + cell, one warp: m-tile mi, n-tiles n0..n0+NCNT.
// Packed operands: one uint4 per (row,kc) for A, one per (nt,kc) for W.
// 3-product bf16 split -> shfl gate exchange -> in-register cell -> packed h writes.
template<int NCNT>
__device__ __forceinline__ void mma_cell(
    const u16* __restrict__ A, const u16* __restrict__ W,
    const float* __restrict__ bias, float* __restrict__ cst,
    u16* dA1,                         // null for L2 (k base 44)
    u16* dA2, int colbase,
    float* ghb,                       // null unless L2
    int mi, int n0, int lane)
{
    const int g  = lane >> 2;
    const int tq = lane & 3;
    float acc[NCNT][4];
    #pragma unroll
    for (int i = 0; i < NCNT; ++i) {
        acc[i][0] = 0.f; acc[i][1] = 0.f; acc[i][2] = 0.f; acc[i][3] = 0.f;
    }
    const int ar0 = (mi*16 + g)*RS + tq*8;
    const int ar1 = ar0 + 8*RS;
    #pragma unroll
    for (int kc = 0; kc < 5; ++kc) {
        const int ka = kc * 32;
        uint4 ra = *(const uint4*)(A + ar0 + ka);
        uint4 rb = *(const uint4*)(A + ar1 + ka);
        #pragma unroll
        for (int nt = 0; nt < NCNT; ++nt) {
            uint4 w = *(const uint4*)(W + ((n0 + nt)*8 + g)*RS + tq*8 + ka);
            mma16816(acc[nt][0],acc[nt][1],acc[nt][2],acc[nt][3],
                     ra.x, rb.x, ra.z, rb.z, w.x, w.z);   // hi*hi
            mma16816(acc[nt][0],acc[nt][1],acc[nt][2],acc[nt][3],
                     ra.x, rb.x, ra.z, rb.z, w.y, w.w);   // hi*lo
            mma16816(acc[nt][0],acc[nt][1],acc[nt][2],acc[nt][3],
                     ra.y, rb.y, ra.w, rb.w, w.x, w.z);   // lo*hi
        }
    }

    const int odd = tq & 1;
    const int row = mi*16 + (odd ? 8 : 0) + g;
    #pragma unroll
    for (int nt = 0; nt < NCNT; ++nt) {
        const int C = (n0 + nt) * 8;
        const int u = 2*(n0 + nt) + (tq >> 1);
        const float4 bb = *(const float4*)(bias + C + ((tq & 2) << 1));
        float s0 = odd ? acc[nt][0] : acc[nt][2];
        float s1 = odd ? acc[nt][1] : acc[nt][3];
        float e0 = __shfl_xor_sync(0xffffffffu, s0, 1);
        float e1 = __shfl_xor_sync(0xffffffffu, s1, 1);
        float zi, zj, zf, zo;
        if (odd) { zi = e0;         zj = e1;         zf = acc[nt][2]; zo = acc[nt][3]; }
        else     { zi = acc[nt][0]; zj = acc[nt][1]; zf = e0;         zo = e1;         }
        float h = cellone(zi + bb.x, zj + bb.y, zf + bb.z, zo + bb.w, cst[nt]);
        u16 hh, hl; bsplit(h, hh, hl);
        const int o2 = pk_off(colbase + u, 0);
        dA2[row*RS + o2]     = hh;
        dA2[row*RS + o2 + 2] = hl;
        if (dA1) {
            const int o1 = pk_off(44 + u, 0);
            dA1[row*RS + o1]     = hh;
            dA1[row*RS + o1 + 2] = hl;
        }
        if (ghb && u < H2D) ghb[(size_t)u * BATCH + row] = h;
    }
}

// ============ x prep: [B][T][D] fp32 -> packed dense rows (80 u16) ============
#define TT 256
__global__ void __launch_bounds__(TT)
xsplit_kernel(const float* __restrict__ x)
{
    __shared__ float s[DIN * 65];
    const int t  = blockIdx.x;
    const int bt = blockIdx.y;
    const int b0 = bt * 64;
    const int tid = threadIdx.x;

    for (int i = tid; i < 64 * DIN; i += TT) {
        int b = i / DIN, d = i - b * DIN;
        s[d * 65 + b] = x[((size_t)(b0 + b) * T_STEPS + t) * DIN + d];
    }
    __syncthreads();
    const size_t base = ((size_t)t * NBLK + bt) * (64*80);
    for (int i = tid; i < 64*80; i += TT) {
        int b = i / 80, o = i - b * 80;
        // inverse map dense offset -> (k, half)
        int k, half;
        if (o < 64) {
            int kc = o >> 5, w = o & 31;
            int tq = w >> 3, r8 = w & 7;
            int grp = (r8 >> 2) & 1; half = (r8 >> 1) & 1;
            int pair = tq + 4*grp;
            k = kc*16 + pair*2 + (r8 & 1);
        } else {
            int w = o - 64;
            int pair = w >> 2; half = (w >> 1) & 1;
            k = 32 + pair*2 + (w & 1);
        }
        float v = (k < DIN) ? s[k * 65 + b] : 0.f;
        u16 hi, lo; bsplit(v, hi, lo);
        g_xp[base + i] = half ? lo : hi;
    }
}

// =============================== LSTM kernel ===============================
extern __shared__ char smc[];

__global__ void __launch_bounds__(NT)
lstm_kernel(const float* __restrict__ fw_W1, const float* __restrict__ fw_b1,
            const float* __restrict__ fw_W2, const float* __restrict__ fw_b2,
            const float* __restrict__ bw_W1, const float* __restrict__ bw_b1,
            const float* __restrict__ bw_W2, const float* __restrict__ bw_b2)
{
    const int dir = blockIdx.y;
    const int bti = blockIdx.x;
    const int b0g = bti * BT;
    const int tid = threadIdx.x;

    float* b1s = (float*)(smc + B1_OFF);
    float* b2s = (float*)(smc + B2_OFF);
    u16* W1s = (u16*)(smc + W1_OFF);
    u16* W2s = (u16*)(smc + W2_OFF);
    u16* A1  = (u16*)(smc + A1_OFF);   // [2][64*RS]
    u16* A2  = (u16*)(smc + A2_OFF);

    const float* W1g = dir ? bw_W1 : fw_W1;
    const float* b1g = dir ? bw_b1 : fw_b1;
    const float* W2g = dir ? bw_W2 : fw_W2;
    const float* b2g = dir ? bw_b2 : fw_b2;

    // ---- prologue: zero A buffers ----
    for (int i = tid; i < 2*ABUF; i += NT) { A1[i] = 0; A2[i] = 0; }

    // W1 packed: row n (gate col), k-map: k<39 = x dim k; 44<=k<79 = h1 unit k-44
    for (int i = tid; i < N1*RS; i += NT) {
        int n = i / RS, j = i - n * RS;
        int kc = j >> 5, w = j & 31;
        int tq = w >> 3, r8 = w & 7;
        int grp = (r8 >> 2) & 1, half = (r8 >> 1) & 1, odd = r8 & 1;
        int k = kc*16 + (tq + 4*grp)*2 + odd;
        int u = n >> 2, gg = n & 3;
        float v = 0.f;
        if (u < H1D) {
            int col = gg*H1D + u;
            int kr = -1;
            if (k < DIN) kr = k;
            else if (k >= 44 && k < 44 + H1D) kr = DIN + (k - 44);
            if (kr >= 0) v = W1g[kr*140 + col];
        }
        u16 hi, lo; bsplit(v, hi, lo);
        W1s[i] = half ? lo : hi;
    }
    // W2 packed: k<35 = h1 unit k; 36<=k<66 = h2 unit k-36
    for (int i = tid; i < N2*RS; i += NT) {
        int n = i / RS, j = i - n * RS;
        int kc = j >> 5, w = j & 31;
        int tq = w >> 3, r8 = w & 7;
        int grp = (r8 >> 2) & 1, half = (r8 >> 1) & 1, odd = r8 & 1;
        int k = kc*16 + (tq + 4*grp)*2 + odd;
        int u = n >> 2, gg = n & 3;
        float v = 0.f;
        if (u < H2D) {
            int col = gg*H2D + u;
            int kr = -1;
            if (k < H1D) kr = k;
            else if (k >= 36 && k < 36 + H2D) kr = H1D + (k - 36);
            if (kr >= 0) v = W2g[kr*120 + col];
        }
        u16 hi, lo; bsplit(v, hi, lo);
        W2s[i] = half ? lo : hi;
    }
    for (int i = tid; i < N1; i += NT) {
        int u = i >> 2, gg = i & 3;
        b1s[i] = (u < H1D) ? b1g[gg*H1D + u] : 0.f;
    }
    for (int i = tid; i < N2; i += NT) {
        int u = i >> 2, gg = i & 3;
        b2s[i] = (u < H2D) ? b2g[gg*H2D + u] : 0.f;
    }
    // stage x[0] into A1 buffer 1 (= read buffer of tick 0)
    {
        const int tx0 = dir ? (T_STEPS - 1) : 0;
        const ull* src = (const ull*)(g_xp + ((size_t)tx0 * NBLK + bti) * (64*80));
        ull* dst = (ull*)(A1 + ABUF);
        for (int i = tid; i < 64*20; i += NT) {
            int r = i / 20, j = i - r * 20;
            int aj = (j < 16) ? j : 16 + (j - 16) * 2;
            dst[r*40 + aj] = src[r*20 + j];
        }
    }
    __syncthreads();

    const int warp = tid >> 5, lane = tid & 31;
    float cst[6] = {0.f,0.f,0.f,0.f,0.f,0.f};

    // roles: warps 0..11 = L1 (mi = w&3, ngp = w>>2, NCNT=6, n0=ngp*6)
    //        warps 12..23 = L2 (w2=w-12: mi=w2&3, ngp=w2>>2; NCNT 6,5,5; n0 0,6,11)
    //        warp 24 = x stager
    for (int tk = 0; tk <= T_STEPS; ++tk) {
        const int wb = tk & 1, rb = wb ^ 1;

        if (warp < 12) {
            if (tk < T_STEPS) {
                const int mi = warp & 3, ngp = warp >> 2;
                mma_cell<6>(A1 + rb*ABUF, W1s, b1s, cst,
                            A1 + wb*ABUF,
                            A2 + wb*ABUF, 0,
                            (float*)0, mi, ngp*6, lane);
            }
        } else if (warp < 24) {
            if (tk >= 1) {
                const int w2 = warp - 12;
                const int mi = w2 & 3, ngp = w2 >> 2;
                const int tx = dir ? (T_STEPS - tk) : (tk - 1);
                float* ghb = g_hbuf + ((size_t)(tx*60 + dir*H2D))*BATCH + b0g;
                if (ngp == 0)
                    mma_cell<6>(A2 + rb*ABUF, W2s, b2s, cst, (u16*)0,
                                A2 + wb*ABUF, 36, ghb, mi, 0, lane);
                else if (ngp == 1)
                    mma_cell<5>(A2 + rb*ABUF, W2s, b2s, cst, (u16*)0,
                                A2 + wb*ABUF, 36, ghb, mi, 6, lane);
                else
                    mma_cell<5>(A2 + rb*ABUF, W2s, b2s, cst, (u16*)0,
                                A2 + wb*ABUF, 36, ghb, mi, 11, lane);
            }
        } else {
            if (tk + 1 < T_STEPS) {
                // stage x[tk+1] into A1[wb] x-region (disjoint from L1 h1 writes)
                const int txn = dir ? (T_STEPS - 2 - tk) : (tk + 1);
                const ull* src = (const ull*)(g_xp + ((size_t)txn * NBLK + bti) * (64*80));
                ull* dst = (ull*)(A1 + wb*ABUF);
                for (int i = lane; i < 64*20; i += 32) {
                    int r = i / 20, j = i - r * 20;
                    int aj = (j < 16) ? j : 16 + (j - 16) * 2;
                    dst[r*40 + aj] = src[r*20 + j];
                }
            }
        }
        __syncthreads();
    }
}

// =============================== FC head (unchanged, passing) ===============================
#define FCT 128
#define FOFF_W1 0
#define FOFF_W2 (FOFF_W1 + 60*52)
#define FOFF_W3 (FOFF_W2 + 50*40)
#define FOFF_B1 (FOFF_W3 + 80)
#define FOFF_B2 (FOFF_B1 + 52)
#define FOFF_B3 (FOFF_B2 + 40)
#define FSM_FLOATS (FOFF_B3 + 4)

__global__ void __launch_bounds__(FCT)
fc_kernel(const float* __restrict__ Wf1, const float* __restrict__ bf1,
          const float* __restrict__ Wf2, const float* __restrict__ bf2,
          const float* __restrict__ Wf3, const float* __restrict__ bf3,
          float* __restrict__ out)
{
    extern __shared__ float fsm[];
    float* W1s = fsm + FOFF_W1;
    float* W2s = fsm + FOFF_W2;
    float* W3s = fsm + FOFF_W3;
    float* B1s = fsm + FOFF_B1;
    float* B2s = fsm + FOFF_B2;
    float* B3s = fsm + FOFF_B3;

    const int tid = threadIdx.x;

    for (int i = tid; i < 60*52; i += FCT) {
        int k = i / 52, j = i - k * 52;
        W1s[i] = (j < 50) ? Wf1[k*50 + j] : 0.f;
    }
    for (int i = tid; i < 50*40; i += FCT) W2s[i] = Wf2[i];
    for (int i = tid; i < 80;    i += FCT) W3s[i] = Wf3[i];
    for (int i = tid; i < 52;    i += FCT) B1s[i] = (i < 50) ? bf1[i] : 0.f;
    for (int i = tid; i < 40;    i += FCT) B2s[i] = bf2[i];
    for (int i = tid; i < 2;     i += FCT) B3s[i] = bf3[i];
    __syncthreads();

    const int bi = blockIdx.x & 31;
    const int t  = blockIdx.x >> 5;
    const int b0 = bi * FCT;
    const float* __restrict__ hb = &g_hbuf[(size_t)t * 60 * BATCH + b0 + tid];

    ull acc1[26];
    #pragma unroll
    for (int j = 0; j < 26; ++j) acc1[j] = pack2(B1s[2*j], B1s[2*j+1]);
    #pragma unroll 4
    for (int k = 0; k < 60; ++k) {
        float v = hb[(size_t)k * BATCH];
        ull vv = pack2(v, v);
        #pragma unroll
        for (int j = 0; j < 13; ++j) {
            ulonglong2 w = *(const ulonglong2*)(W1s + k*52 + j*4);
            acc1[2*j]   = fma2(vv, w.x, acc1[2*j]);
            acc1[2*j+1] = fma2(vv, w.y, acc1[2*j+1]);
        }
    }
    float a1[52];
    #pragma unroll
    for (int j = 0; j < 26; ++j) {
        float lo, hi; unpack2(acc1[j], lo, hi);
        a1[2*j]   = fmaxf(lo, 0.f);
        a1[2*j+1] = fmaxf(hi, 0.f);
    }

    ull acc2[20];
    #pragma unroll
    for (int j = 0; j < 20; ++j) acc2[j] = pack2(B2s[2*j], B2s[2*j+1]);
    #pragma unroll 5
    for (int k = 0; k < 50; ++k) {
        ull vv = pack2(a1[k], a1[k]);
        #pragma unroll
        for (int j = 0; j < 10; ++j) {
            ulonglong2 w = *(const ulonglong2*)(W2s + k*40 + j*4);
            acc2[2*j]   = fma2(vv, w.x, acc2[2*j]);
            acc2[2*j+1] = fma2(vv, w.y, acc2[2*j+1]);
        }
    }
    float a2[40];
    #pragma unroll
    for (int j = 0; j < 20; ++j) {
        float lo, hi; unpack2(acc2[j], lo, hi);
        a2[2*j]   = fmaxf(lo, 0.f);
        a2[2*j+1] = fmaxf(hi, 0.f);
    }

    float o0 = B3s[0], o1 = B3s[1];
    #pragma unroll
    for (int k = 0; k < 40; ++k) {
        o0 = fmaf(a2[k], W3s[2*k + 0], o0);
        o1 = fmaf(a2[k], W3s[2*k + 1], o1);
    }
    float2 ov = make_float2(o0, o1);
    *(float2*)(&out[((size_t)(b0 + tid) * T_STEPS + t) * 2]) = ov;
}

// ============================================================================
extern "C" void kernel_launch(void* const* d_in, const int* in_sizes, int n_in,
                              void* d_out, int out_size)
{
    const float* x     = (const float*)d_in[0];
    const float* fw_W1 = (const float*)d_in[1];
    const float* fw_b1 = (const float*)d_in[2];
    const float* fw_W2 = (const float*)d_in[3];
    const float* fw_b2 = (const float*)d_in[4];
    const float* bw_W1 = (const float*)d_in[5];
    const float* bw_b1 = (const float*)d_in[6];
    const float* bw_W2 = (const float*)d_in[7];
    const float* bw_b2 = (const float*)d_in[8];
    const float* Wf1   = (const float*)d_in[9];
    const float* bf1   = (const float*)d_in[10];
    const float* Wf2   = (const float*)d_in[11];
    const float* bf2   = (const float*)d_in[12];
    const float* Wf3   = (const float*)d_in[13];
    const float* bf3   = (const float*)d_in[14];

    cudaFuncSetAttribute(lstm_kernel, cudaFuncAttributeMaxDynamicSharedMemorySize,
                         SMEM_BYTES);
    cudaFuncSetAttribute(fc_kernel, cudaFuncAttributeMaxDynamicSharedMemorySize,
                         FSM_FLOATS * (int)sizeof(float));

    xsplit_kernel<<<dim3(T_STEPS, NBLK), TT>>>(x);

    lstm_kernel<<<dim3(NBLK, 2), NT, SMEM_BYTES>>>(
        fw_W1, fw_b1, fw_W2, fw_b2, bw_W1, bw_b1, bw_W2, bw_b2);

    fc_kernel<<<32 * T_STEPS, FCT, FSM_FLOATS * sizeof(float)>>>(
        Wf1, bf1, Wf2, bf2, Wf3, bf3, (float*)d_out);
}

// round 16
// speedup vs baseline: 1.3828x; 1.3828x over previous
#include <cuda_runtime.h>
#include <cuda_bf16.h>
#include <math.h>

#define T_STEPS 300
#define DIN 39
#define H1D 35
#define H2D 30
#define BT 64
#define BATCH 4096
#define NBLK (BATCH/BT)
#define NT 800           // 12 L1 warps + 12 L2 warps + 1 stager

#define KP 88            // row stride (bf16): (row*44+tq)%32 covers all banks -> conflict-free
#define N1 144           // L1 gate cols (36 units * 4)
#define N2 128           // L2 gate cols (32 units * 4)

// smem byte offsets (all 16B aligned)
#define B1_OFF   0
#define B2_OFF   576
#define W1H_OFF  1088
#define W1L_OFF  26432
#define W2H_OFF  51776
#define W2L_OFF  74304
#define A1H_OFF  96832     // 2 buffers of 64*KP u16 (11264 B each)
#define A1L_OFF  119360
#define A2H_OFF  141888
#define A2L_OFF  164416
#define SMEM_BYTES 186944
#define ABUF (64*KP)       // u16 elements per A buffer

typedef unsigned long long ull;
typedef unsigned short u16;
typedef unsigned int u32;

// scratch: LSTM hidden states [T][60][B]  (fw units [0,30), bw [30,60))
__device__ float g_hbuf[(size_t)BATCH * T_STEPS * 60];
// pre-split transposed input, A-operand layout [T][btile][64 rows][40 cols]
__device__ u16 g_xhi[(size_t)T_STEPS * NBLK * 64 * 40];
__device__ u16 g_xlo[(size_t)T_STEPS * NBLK * 64 * 40];

// ---------------- helpers ----------------
__device__ __forceinline__ ull fma2(ull a, ull b, ull c) {
    ull d;
    asm("fma.rn.f32x2 %0, %1, %2, %3;" : "=l"(d) : "l"(a), "l"(b), "l"(c));
    return d;
}
__device__ __forceinline__ ull pack2(float lo, float hi) {
    ull d;
    asm("mov.b64 %0, {%1, %2};" : "=l"(d) : "f"(lo), "f"(hi));
    return d;
}
__device__ __forceinline__ void unpack2(ull v, float& lo, float& hi) {
    asm("mov.b64 {%0, %1}, %2;" : "=f"(lo), "=f"(hi) : "l"(v));
}
__device__ __forceinline__ float sigf(float x) {
    return __fdividef(1.0f, 1.0f + __expf(-x));
}
__device__ __forceinline__ float tanhfast(float x) {
    return 2.0f * sigf(2.0f * x) - 1.0f;
}
__device__ __forceinline__ float cellone(float zi, float zj, float zf, float zo, float& c) {
    c = sigf(zf + 1.0f) * c + sigf(zi) * tanhfast(zj);
    return sigf(zo) * tanhfast(c);
}
__device__ __forceinline__ void bsplit(float v, u16& hi, u16& lo) {
    __nv_bfloat16 h = __float2bfloat16(v);
    float r = v - __bfloat162float(h);
    __nv_bfloat16 l = __float2bfloat16(r);
    hi = __bfloat16_as_ushort(h);
    lo = __bfloat16_as_ushort(l);
}

__device__ __forceinline__ void mma16816(float& c0, float& c1, float& c2, float& c3,
                                         u32 a0, u32 a1, u32 a2, u32 a3,
                                         u32 b0, u32 b1)
{
    asm volatile("mma.sync.aligned.m16n8k16.row.col.f32.bf16.bf16.f32 "
                 "{%0,%1,%2,%3},{%4,%5,%6,%7},{%8,%9},{%0,%1,%2,%3};"
                 : "+f"(c0), "+f"(c1), "+f"(c2), "+f"(c3)
                 : "r"(a0), "r"(a1), "r"(a2), "r"(a3), "r"(b0), "r"(b1));
}

// Fused MMA + cell for one warp covering m-tile mi, n-tiles n0..n0+NCNT.
// R16: A fragments preloaded into registers once; nt-outer loop runs
// W-loads -> MMA -> immediate per-tile cell epilogue so MUFU work interleaves
// with the next tile's LDS/MMA instead of bunching after the barrier.
// Per acc tile the FP sequence is identical to R13 (kc ascending; hi*hi,
// hi*lo, lo*hi) -> bit-identical results.
template<int NCNT>
__device__ __forceinline__ void mma_cell(
    const u16* __restrict__ Ah, const u16* __restrict__ Al,
    const u16* __restrict__ Wh, const u16* __restrict__ Wl,
    const float* __restrict__ bias, float* __restrict__ cst,
    u16* dA1h, u16* dA1l,            // null for L2
    u16* dA2h, u16* dA2l, int colbase,
    float* ghb,                       // null unless L2 (base for this tick)
    int mi, int n0, int lane)
{
    const int g  = lane >> 2;
    const int tq = lane & 3;
    const int t2 = tq * 2;
    const int ar0 = (mi*16 + g)*KP + t2;
    const int ar1 = ar0 + 8*KP;

    // preload all A fragments (40 regs)
    u32 ah[5][4], al[5][4];
    #pragma unroll
    for (int kc = 0; kc < 5; ++kc) {
        const int ka = kc * 16;
        ah[kc][0] = *(const u32*)(Ah + ar0 + ka);
        ah[kc][1] = *(const u32*)(Ah + ar1 + ka);
        ah[kc][2] = *(const u32*)(Ah + ar0 + ka + 8);
        ah[kc][3] = *(const u32*)(Ah + ar1 + ka + 8);
        al[kc][0] = *(const u32*)(Al + ar0 + ka);
        al[kc][1] = *(const u32*)(Al + ar1 + ka);
        al[kc][2] = *(const u32*)(Al + ar0 + ka + 8);
        al[kc][3] = *(const u32*)(Al + ar1 + ka + 8);
    }

    const int odd = tq & 1;
    const int row = mi*16 + (odd ? 8 : 0) + g;

    #pragma unroll
    for (int nt = 0; nt < NCNT; ++nt) {
        float a0 = 0.f, a1v = 0.f, a2v = 0.f, a3v = 0.f;
        const int wbase = ((n0 + nt)*8 + g)*KP + t2;
        #pragma unroll
        for (int kc = 0; kc < 5; ++kc) {
            const int wr = wbase + kc*16;
            u32 bh0 = *(const u32*)(Wh + wr);
            u32 bh1 = *(const u32*)(Wh + wr + 8);
            u32 bl0 = *(const u32*)(Wl + wr);
            u32 bl1 = *(const u32*)(Wl + wr + 8);
            mma16816(a0,a1v,a2v,a3v, ah[kc][0],ah[kc][1],ah[kc][2],ah[kc][3], bh0,bh1);
            mma16816(a0,a1v,a2v,a3v, ah[kc][0],ah[kc][1],ah[kc][2],ah[kc][3], bl0,bl1);
            mma16816(a0,a1v,a2v,a3v, al[kc][0],al[kc][1],al[kc][2],al[kc][3], bh0,bh1);
        }
        // per-tile epilogue (identical math to R13)
        const int C = (n0 + nt) * 8;
        const int u = 2*(n0 + nt) + (tq >> 1);
        const float4 bb = *(const float4*)(bias + C + ((tq & 2) << 1));
        float s0 = odd ? a0 : a2v;
        float s1 = odd ? a1v : a3v;
        float e0 = __shfl_xor_sync(0xffffffffu, s0, 1);
        float e1 = __shfl_xor_sync(0xffffffffu, s1, 1);
        float zi, zj, zf, zo;
        if (odd) { zi = e0;  zj = e1;  zf = a2v; zo = a3v; }
        else     { zi = a0;  zj = a1v; zf = e0;  zo = e1;  }
        float h = cellone(zi + bb.x, zj + bb.y, zf + bb.z, zo + bb.w, cst[nt]);
        u16 hh, hl; bsplit(h, hh, hl);
        const int idx = row*KP + colbase + u;
        dA2h[idx] = hh;
        dA2l[idx] = hl;
        if (dA1h) { dA1h[row*KP + u] = hh; dA1l[row*KP + u] = hl; }
        if (ghb && u < H2D) ghb[(size_t)u * BATCH + row] = h;
    }
}

// ============ x prep: [B][T][D] fp32 -> [T][btile][64][40] bf16 hi/lo ============
#define TT 256
__global__ void __launch_bounds__(TT)
xsplit_kernel(const float* __restrict__ x)
{
    __shared__ float s[DIN * 65];
    const int t  = blockIdx.x;
    const int bt = blockIdx.y;
    const int b0 = bt * 64;
    const int tid = threadIdx.x;

    for (int i = tid; i < 64 * DIN; i += TT) {
        int b = i / DIN, d = i - b * DIN;
        s[d * 65 + b] = x[((size_t)(b0 + b) * T_STEPS + t) * DIN + d];
    }
    __syncthreads();
    const size_t base = ((size_t)t * NBLK + bt) * 2560;
    for (int i = tid; i < 2560; i += TT) {
        int b = i / 40, d = i - b * 40;
        float v = (d < DIN) ? s[d * 65 + b] : 0.f;
        u16 hi, lo; bsplit(v, hi, lo);
        g_xhi[base + i] = hi;
        g_xlo[base + i] = lo;
    }
}

// =============================== LSTM kernel ===============================
extern __shared__ char smc[];

__global__ void __launch_bounds__(NT)
lstm_kernel(const float* __restrict__ fw_W1, const float* __restrict__ fw_b1,
            const float* __restrict__ fw_W2, const float* __restrict__ fw_b2,
            const float* __restrict__ bw_W1, const float* __restrict__ bw_b1,
            const float* __restrict__ bw_W2, const float* __restrict__ bw_b2)
{
    const int dir = blockIdx.y;
    const int bti = blockIdx.x;
    const int b0g = bti * BT;
    const int tid = threadIdx.x;

    float* b1s = (float*)(smc + B1_OFF);
    float* b2s = (float*)(smc + B2_OFF);
    u16* W1h = (u16*)(smc + W1H_OFF);
    u16* W1l = (u16*)(smc + W1L_OFF);
    u16* W2h = (u16*)(smc + W2H_OFF);
    u16* W2l = (u16*)(smc + W2L_OFF);
    u16* A1h = (u16*)(smc + A1H_OFF);   // [2][64*KP]
    u16* A1l = (u16*)(smc + A1L_OFF);
    u16* A2h = (u16*)(smc + A2H_OFF);
    u16* A2l = (u16*)(smc + A2L_OFF);

    const float* W1g = dir ? bw_W1 : fw_W1;
    const float* b1g = dir ? bw_b1 : fw_b1;
    const float* W2g = dir ? bw_W2 : fw_W2;
    const float* b2g = dir ? bw_b2 : fw_b2;

    // ---- prologue ----
    for (int i = tid; i < 2*ABUF; i += NT) { A1h[i]=0; A1l[i]=0; A2h[i]=0; A2l[i]=0; }

    // W1: n-major cols 0..143 (unit-major gates); k-rows: 0..34 h1, 35 pad, 36..74 x, 75..87 pad
    for (int i = tid; i < N1*KP; i += NT) {
        int n = i / KP, c = i - n * KP;
        int u = n >> 2, gg = n & 3;
        float v = 0.f;
        if (u < H1D) {
            int col = gg*H1D + u;
            int kr = -1;
            if (c < H1D) kr = 39 + c;
            else if (c >= 36 && c < 36 + DIN) kr = c - 36;
            if (kr >= 0) v = W1g[kr*140 + col];
        }
        u16 hi, lo; bsplit(v, hi, lo);
        W1h[i] = hi; W1l[i] = lo;
    }
    // W2: cols 0..127; k-rows: 0..34 h1, 35 pad, 36..65 h2, 66..87 pad
    for (int i = tid; i < N2*KP; i += NT) {
        int n = i / KP, c = i - n * KP;
        int u = n >> 2, gg = n & 3;
        float v = 0.f;
        if (u < H2D) {
            int col = gg*H2D + u;
            int kr = -1;
            if (c < H1D) kr = c;
            else if (c >= 36 && c < 36 + H2D) kr = H1D + (c - 36);
            if (kr >= 0) v = W2g[kr*120 + col];
        }
        u16 hi, lo; bsplit(v, hi, lo);
        W2h[i] = hi; W2l[i] = lo;
    }
    for (int i = tid; i < N1; i += NT) {
        int u = i >> 2, gg = i & 3;
        b1s[i] = (u < H1D) ? b1g[gg*H1D + u] : 0.f;
    }
    for (int i = tid; i < N2; i += NT) {
        int u = i >> 2, gg = i & 3;
        b2s[i] = (u < H2D) ? b2g[gg*H2D + u] : 0.f;
    }
    // stage x[0] into A1 buffer 1 (= read buffer of tick 0)
    {
        const int tx0 = dir ? (T_STEPS - 1) : 0;
        const size_t base = ((size_t)tx0 * NBLK + bti) * 2560;
        for (int i = tid; i < 2560; i += NT) {
            int r = i / 40, d = i - r * 40;
            A1h[ABUF + r*KP + 36 + d] = g_xhi[base + i];
            A1l[ABUF + r*KP + 36 + d] = g_xlo[base + i];
        }
    }
    __syncthreads();

    const int warp = tid >> 5, lane = tid & 31;
    float cst[6] = {0.f,0.f,0.f,0.f,0.f,0.f};

    // roles: warps 0..11 = L1 (mi = w&3, ngp = w>>2, NCNT=6, n0=ngp*6)
    //        warps 12..23 = L2 (w2=w-12: mi = w2&3, ngp = w2>>2; NCNT 6,5,5; n0 0,6,11)
    //        warp 24 = x stager
    for (int tk = 0; tk <= T_STEPS; ++tk) {
        const int wb = tk & 1, rb = wb ^ 1;

        if (warp < 12) {
            if (tk < T_STEPS) {
                const int mi = warp & 3, ngp = warp >> 2;
                mma_cell<6>(A1h + rb*ABUF, A1l + rb*ABUF, W1h, W1l,
                            b1s, cst,
                            A1h + wb*ABUF, A1l + wb*ABUF,
                            A2h + wb*ABUF, A2l + wb*ABUF, 0,
                            (float*)0, mi, ngp*6, lane);
            }
        } else if (warp < 24) {
            if (tk >= 1) {
                const int w2 = warp - 12;
                const int mi = w2 & 3, ngp = w2 >> 2;
                const int tx = dir ? (T_STEPS - tk) : (tk - 1);
                float* ghb = g_hbuf + ((size_t)(tx*60 + dir*H2D))*BATCH + b0g;
                if (ngp == 0)
                    mma_cell<6>(A2h + rb*ABUF, A2l + rb*ABUF, W2h, W2l,
                                b2s, cst, (u16*)0, (u16*)0,
                                A2h + wb*ABUF, A2l + wb*ABUF, 36,
                                ghb, mi, 0, lane);
                else if (ngp == 1)
                    mma_cell<5>(A2h + rb*ABUF, A2l + rb*ABUF, W2h, W2l,
                                b2s, cst, (u16*)0, (u16*)0,
                                A2h + wb*ABUF, A2l + wb*ABUF, 36,
                                ghb, mi, 6, lane);
                else
                    mma_cell<5>(A2h + rb*ABUF, A2l + rb*ABUF, W2h, W2l,
                                b2s, cst, (u16*)0, (u16*)0,
                                A2h + wb*ABUF, A2l + wb*ABUF, 36,
                                ghb, mi, 11, lane);
            }
        } else {
            if (tk + 1 < T_STEPS) {
                // stage x[tk+1] into A1[wb] x-region (read next tick)
                const int txn = dir ? (T_STEPS - 2 - tk) : (tk + 1);
                const size_t base = ((size_t)txn * NBLK + bti) * 2560;
                u16* dh = A1h + wb*ABUF;
                u16* dl = A1l + wb*ABUF;
                for (int i = lane; i < 640; i += 32) {
                    int r = i / 10, c = i - r * 10;
                    ((ull*)(dh + r*KP + 36))[c] = ((const ull*)(g_xhi + base + r*40))[c];
                    ((ull*)(dl + r*KP + 36))[c] = ((const ull*)(g_xlo + base + r*40))[c];
                }
            }
        }
        __syncthreads();
    }
}

// =============================== FC head (unchanged, passing) ===============================
#define FCT 128
#define FOFF_W1 0
#define FOFF_W2 (FOFF_W1 + 60*52)
#define FOFF_W3 (FOFF_W2 + 50*40)
#define FOFF_B1 (FOFF_W3 + 80)
#define FOFF_B2 (FOFF_B1 + 52)
#define FOFF_B3 (FOFF_B2 + 40)
#define FSM_FLOATS (FOFF_B3 + 4)

__global__ void __launch_bounds__(FCT)
fc_kernel(const float* __restrict__ Wf1, const float* __restrict__ bf1,
          const float* __restrict__ Wf2, const float* __restrict__ bf2,
          const float* __restrict__ Wf3, const float* __restrict__ bf3,
          float* __restrict__ out)
{
    extern __shared__ float fsm[];
    float* W1s = fsm + FOFF_W1;
    float* W2s = fsm + FOFF_W2;
    float* W3s = fsm + FOFF_W3;
    float* B1s = fsm + FOFF_B1;
    float* B2s = fsm + FOFF_B2;
    float* B3s = fsm + FOFF_B3;

    const int tid = threadIdx.x;

    for (int i = tid; i < 60*52; i += FCT) {
        int k = i / 52, j = i - k * 52;
        W1s[i] = (j < 50) ? Wf1[k*50 + j] : 0.f;
    }
    for (int i = tid; i < 50*40; i += FCT) W2s[i] = Wf2[i];
    for (int i = tid; i < 80;    i += FCT) W3s[i] = Wf3[i];
    for (int i = tid; i < 52;    i += FCT) B1s[i] = (i < 50) ? bf1[i] : 0.f;
    for (int i = tid; i < 40;    i += FCT) B2s[i] = bf2[i];
    for (int i = tid; i < 2;     i += FCT) B3s[i] = bf3[i];
    __syncthreads();

    const int bi = blockIdx.x & 31;
    const int t  = blockIdx.x >> 5;
    const int b0 = bi * FCT;
    const float* __restrict__ hb = &g_hbuf[(size_t)t * 60 * BATCH + b0 + tid];

    ull acc1[26];
    #pragma unroll
    for (int j = 0; j < 26; ++j) acc1[j] = pack2(B1s[2*j], B1s[2*j+1]);
    #pragma unroll 4
    for (int k = 0; k < 60; ++k) {
        float v = hb[(size_t)k * BATCH];
        ull vv = pack2(v, v);
        #pragma unroll
        for (int j = 0; j < 13; ++j) {
            ulonglong2 w = *(const ulonglong2*)(W1s + k*52 + j*4);
            acc1[2*j]   = fma2(vv, w.x, acc1[2*j]);
            acc1[2*j+1] = fma2(vv, w.y, acc1[2*j+1]);
        }
    }
    float a1[52];
    #pragma unroll
    for (int j = 0; j < 26; ++j) {
        float lo, hi; unpack2(acc1[j], lo, hi);
        a1[2*j]   = fmaxf(lo, 0.f);
        a1[2*j+1] = fmaxf(hi, 0.f);
    }

    ull acc2[20];
    #pragma unroll
    for (int j = 0; j < 20; ++j) acc2[j] = pack2(B2s[2*j], B2s[2*j+1]);
    #pragma unroll 5
    for (int k = 0; k < 50; ++k) {
        ull vv = pack2(a1[k], a1[k]);
        #pragma unroll
        for (int j = 0; j < 10; ++j) {
            ulonglong2 w = *(const ulonglong2*)(W2s + k*40 + j*4);
            acc2[2*j]   = fma2(vv, w.x, acc2[2*j]);
            acc2[2*j+1] = fma2(vv, w.y, acc2[2*j+1]);
        }
    }
    float a2[40];
    #pragma unroll
    for (int j = 0; j < 20; ++j) {
        float lo, hi; unpack2(acc2[j], lo, hi);
        a2[2*j]   = fmaxf(lo, 0.f);
        a2[2*j+1] = fmaxf(hi, 0.f);
    }

    float o0 = B3s[0], o1 = B3s[1];
    #pragma unroll
    for (int k = 0; k < 40; ++k) {
        o0 = fmaf(a2[k], W3s[2*k + 0], o0);
        o1 = fmaf(a2[k], W3s[2*k + 1], o1);
    }
    float2 ov = make_float2(o0, o1);
    *(float2*)(&out[((size_t)(b0 + tid) * T_STEPS + t) * 2]) = ov;
}

// ============================================================================
extern "C" void kernel_launch(void* const* d_in, const int* in_sizes, int n_in,
                              void* d_out, int out_size)
{
    const float* x     = (const float*)d_in[0];
    const float* fw_W1 = (const float*)d_in[1];
    const float* fw_b1 = (const float*)d_in[2];
    const float* fw_W2 = (const float*)d_in[3];
    const float* fw_b2 = (const float*)d_in[4];
    const float* bw_W1 = (const float*)d_in[5];
    const float* bw_b1 = (const float*)d_in[6];
    const float* bw_W2 = (const float*)d_in[7];
    const float* bw_b2 = (const float*)d_in[8];
    const float* Wf1   = (const float*)d_in[9];
    const float* bf1   = (const float*)d_in[10];
    const float* Wf2   = (const float*)d_in[11];
    const float* bf2   = (const float*)d_in[12];
    const float* Wf3   = (const float*)d_in[13];
    const float* bf3   = (const float*)d_in[14];

    cudaFuncSetAttribute(lstm_kernel, cudaFuncAttributeMaxDynamicSharedMemorySize,
                         SMEM_BYTES);
    cudaFuncSetAttribute(fc_kernel, cudaFuncAttributeMaxDynamicSharedMemorySize,
                         FSM_FLOATS * (int)sizeof(float));

    xsplit_kernel<<<dim3(T_STEPS, NBLK), TT>>>(x);

    lstm_kernel<<<dim3(NBLK, 2), NT, SMEM_BYTES>>>(
        fw_W1, fw_b1, fw_W2, fw_b2, bw_W1, bw_b1, bw_W2, bw_b2);

    fc_kernel<<<32 * T_STEPS, FCT, FSM_FLOATS * sizeof(float)>>>(
        Wf1, bf1, Wf2, bf2, Wf3, bf3, (float*)d_out);
}

// round 17
// speedup vs baseline: 1.4539x; 1.0514x over previous
#include <cuda_runtime.h>
#include <cuda_bf16.h>
#include <math.h>

#define T_STEPS 300
#define DIN 39
#define H1D 35
#define H2D 30
#define BT 64
#define BATCH 4096
#define NBLK (BATCH/BT)
#define NT 800           // 12 L1 warps + 12 L2 warps + 1 stager

#define KP 88            // row stride (bf16): (row*44+tq)%32 covers all banks -> conflict-free
#define N1 144           // L1 gate cols (36 units * 4)
#define N2 128           // L2 gate cols (32 units * 4)

// smem byte offsets (all 16B aligned)
#define B1_OFF   0
#define B2_OFF   576
#define W1H_OFF  1088
#define W1L_OFF  26432
#define W2H_OFF  51776
#define W2L_OFF  74304
#define A1H_OFF  96832     // 2 buffers of 64*KP u16 (11264 B each)
#define A1L_OFF  119360
#define A2H_OFF  141888
#define A2L_OFF  164416
#define SMEM_BYTES 186944
#define ABUF (64*KP)       // u16 elements per A buffer

typedef unsigned long long ull;
typedef unsigned short u16;
typedef unsigned int u32;

// scratch: LSTM hidden states [T][60][B]  (fw units [0,30), bw [30,60))
__device__ float g_hbuf[(size_t)BATCH * T_STEPS * 60];
// pre-split transposed input, A-operand layout [T][btile][64 rows][40 cols]
__device__ u16 g_xhi[(size_t)T_STEPS * NBLK * 64 * 40];
__device__ u16 g_xlo[(size_t)T_STEPS * NBLK * 64 * 40];

// ---------------- helpers ----------------
__device__ __forceinline__ ull fma2(ull a, ull b, ull c) {
    ull d;
    asm("fma.rn.f32x2 %0, %1, %2, %3;" : "=l"(d) : "l"(a), "l"(b), "l"(c));
    return d;
}
__device__ __forceinline__ ull pack2(float lo, float hi) {
    ull d;
    asm("mov.b64 %0, {%1, %2};" : "=l"(d) : "f"(lo), "f"(hi));
    return d;
}
__device__ __forceinline__ void unpack2(ull v, float& lo, float& hi) {
    asm("mov.b64 {%0, %1}, %2;" : "=f"(lo), "=f"(hi) : "l"(v));
}
__device__ __forceinline__ float sigf(float x) {
    return __fdividef(1.0f, 1.0f + __expf(-x));
}
__device__ __forceinline__ float tanhfast(float x) {
    return 2.0f * sigf(2.0f * x) - 1.0f;
}
__device__ __forceinline__ float cellone(float zi, float zj, float zf, float zo, float& c) {
    c = sigf(zf + 1.0f) * c + sigf(zi) * tanhfast(zj);
    return sigf(zo) * tanhfast(c);
}
__device__ __forceinline__ void bsplit(float v, u16& hi, u16& lo) {
    __nv_bfloat16 h = __float2bfloat16(v);
    float r = v - __bfloat162float(h);
    __nv_bfloat16 l = __float2bfloat16(r);
    hi = __bfloat16_as_ushort(h);
    lo = __bfloat16_as_ushort(l);
}

__device__ __forceinline__ void mma16816(float& c0, float& c1, float& c2, float& c3,
                                         u32 a0, u32 a1, u32 a2, u32 a3,
                                         u32 b0, u32 b1)
{
    asm volatile("mma.sync.aligned.m16n8k16.row.col.f32.bf16.bf16.f32 "
                 "{%0,%1,%2,%3},{%4,%5,%6,%7},{%8,%9},{%0,%1,%2,%3};"
                 : "+f"(c0), "+f"(c1), "+f"(c2), "+f"(c3)
                 : "r"(a0), "r"(a1), "r"(a2), "r"(a3), "r"(b0), "r"(b1));
}

// Fused MMA + cell for one warp covering m-tile mi, n-tiles n0..n0+NCNT.
// 3-product bf16 split GEMM (K=80) -> shfl gate exchange -> in-register cell
// -> bf16-split h write to A buffers (and optionally g_hbuf).  (R13 body)
template<int NCNT>
__device__ __forceinline__ void mma_cell(
    const u16* __restrict__ Ah, const u16* __restrict__ Al,
    const u16* __restrict__ Wh, const u16* __restrict__ Wl,
    const float* __restrict__ bias, float* __restrict__ cst,
    u16* dA1h, u16* dA1l,            // null for L2
    u16* dA2h, u16* dA2l, int colbase,
    float* ghb,                       // null unless L2 (base for this tick)
    int mi, int n0, int lane)
{
    const int g  = lane >> 2;
    const int tq = lane & 3;
    const int t2 = tq * 2;
    float acc[NCNT][4];
    #pragma unroll
    for (int i = 0; i < NCNT; ++i) {
        acc[i][0] = 0.f; acc[i][1] = 0.f; acc[i][2] = 0.f; acc[i][3] = 0.f;
    }
    const int ar0 = (mi*16 + g)*KP + t2;
    const int ar1 = ar0 + 8*KP;
    #pragma unroll
    for (int kc = 0; kc < 5; ++kc) {
        const int ka = kc * 16;
        u32 ah0 = *(const u32*)(Ah + ar0 + ka);
        u32 ah1 = *(const u32*)(Ah + ar1 + ka);
        u32 ah2 = *(const u32*)(Ah + ar0 + ka + 8);
        u32 ah3 = *(const u32*)(Ah + ar1 + ka + 8);
        u32 al0 = *(const u32*)(Al + ar0 + ka);
        u32 al1 = *(const u32*)(Al + ar1 + ka);
        u32 al2 = *(const u32*)(Al + ar0 + ka + 8);
        u32 al3 = *(const u32*)(Al + ar1 + ka + 8);
        #pragma unroll
        for (int nt = 0; nt < NCNT; ++nt) {
            const int wr = ((n0 + nt)*8 + g)*KP + t2 + ka;
            u32 bh0 = *(const u32*)(Wh + wr);
            u32 bh1 = *(const u32*)(Wh + wr + 8);
            u32 bl0 = *(const u32*)(Wl + wr);
            u32 bl1 = *(const u32*)(Wl + wr + 8);
            mma16816(acc[nt][0],acc[nt][1],acc[nt][2],acc[nt][3], ah0,ah1,ah2,ah3, bh0,bh1);
            mma16816(acc[nt][0],acc[nt][1],acc[nt][2],acc[nt][3], ah0,ah1,ah2,ah3, bl0,bl1);
            mma16816(acc[nt][0],acc[nt][1],acc[nt][2],acc[nt][3], al0,al1,al2,al3, bh0,bh1);
        }
    }

    const int odd  = tq & 1;
    const int row  = (odd ? mi*16 + 8 : mi*16) + g;
    #pragma unroll
    for (int nt = 0; nt < NCNT; ++nt) {
        const int C = (n0 + nt) * 8;
        const int u = 2*(n0 + nt) + (tq >> 1);
        const float4 bb = *(const float4*)(bias + C + ((tq & 2) << 1));
        float s0 = odd ? acc[nt][0] : acc[nt][2];
        float s1 = odd ? acc[nt][1] : acc[nt][3];
        float e0 = __shfl_xor_sync(0xffffffffu, s0, 1);
        float e1 = __shfl_xor_sync(0xffffffffu, s1, 1);
        float zi, zj, zf, zo;
        if (odd) { zi = e0;         zj = e1;         zf = acc[nt][2]; zo = acc[nt][3]; }
        else     { zi = acc[nt][0]; zj = acc[nt][1]; zf = e0;         zo = e1;         }
        float h = cellone(zi + bb.x, zj + bb.y, zf + bb.z, zo + bb.w, cst[nt]);
        u16 hh, hl; bsplit(h, hh, hl);
        const int idx = row*KP + colbase + u;
        dA2h[idx] = hh;
        dA2l[idx] = hl;
        if (dA1h) { dA1h[row*KP + u] = hh; dA1l[row*KP + u] = hl; }
        if (ghb && u < H2D) ghb[(size_t)u * BATCH + row] = h;
    }
}

// ============ x prep: [B][T][D] fp32 -> [T][btile][64][40] bf16 hi/lo ============
#define TT 256
__global__ void __launch_bounds__(TT)
xsplit_kernel(const float* __restrict__ x)
{
    __shared__ float s[DIN * 65];
    const int t  = blockIdx.x;
    const int bt = blockIdx.y;
    const int b0 = bt * 64;
    const int tid = threadIdx.x;

    for (int i = tid; i < 64 * DIN; i += TT) {
        int b = i / DIN, d = i - b * DIN;
        s[d * 65 + b] = x[((size_t)(b0 + b) * T_STEPS + t) * DIN + d];
    }
    __syncthreads();
    const size_t base = ((size_t)t * NBLK + bt) * 2560;
    for (int i = tid; i < 2560; i += TT) {
        int b = i / 40, d = i - b * 40;
        float v = (d < DIN) ? s[d * 65 + b] : 0.f;
        u16 hi, lo; bsplit(v, hi, lo);
        g_xhi[base + i] = hi;
        g_xlo[base + i] = lo;
    }
}

// =============================== LSTM kernel (R13) ===============================
extern __shared__ char smc[];

__global__ void __launch_bounds__(NT)
lstm_kernel(const float* __restrict__ fw_W1, const float* __restrict__ fw_b1,
            const float* __restrict__ fw_W2, const float* __restrict__ fw_b2,
            const float* __restrict__ bw_W1, const float* __restrict__ bw_b1,
            const float* __restrict__ bw_W2, const float* __restrict__ bw_b2)
{
    const int dir = blockIdx.y;
    const int bti = blockIdx.x;
    const int b0g = bti * BT;
    const int tid = threadIdx.x;

    float* b1s = (float*)(smc + B1_OFF);
    float* b2s = (float*)(smc + B2_OFF);
    u16* W1h = (u16*)(smc + W1H_OFF);
    u16* W1l = (u16*)(smc + W1L_OFF);
    u16* W2h = (u16*)(smc + W2H_OFF);
    u16* W2l = (u16*)(smc + W2L_OFF);
    u16* A1h = (u16*)(smc + A1H_OFF);   // [2][64*KP]
    u16* A1l = (u16*)(smc + A1L_OFF);
    u16* A2h = (u16*)(smc + A2H_OFF);
    u16* A2l = (u16*)(smc + A2L_OFF);

    const float* W1g = dir ? bw_W1 : fw_W1;
    const float* b1g = dir ? bw_b1 : fw_b1;
    const float* W2g = dir ? bw_W2 : fw_W2;
    const float* b2g = dir ? bw_b2 : fw_b2;

    // ---- prologue ----
    for (int i = tid; i < 2*ABUF; i += NT) { A1h[i]=0; A1l[i]=0; A2h[i]=0; A2l[i]=0; }

    for (int i = tid; i < N1*KP; i += NT) {
        int n = i / KP, c = i - n * KP;
        int u = n >> 2, gg = n & 3;
        float v = 0.f;
        if (u < H1D) {
            int col = gg*H1D + u;
            int kr = -1;
            if (c < H1D) kr = 39 + c;
            else if (c >= 36 && c < 36 + DIN) kr = c - 36;
            if (kr >= 0) v = W1g[kr*140 + col];
        }
        u16 hi, lo; bsplit(v, hi, lo);
        W1h[i] = hi; W1l[i] = lo;
    }
    for (int i = tid; i < N2*KP; i += NT) {
        int n = i / KP, c = i - n * KP;
        int u = n >> 2, gg = n & 3;
        float v = 0.f;
        if (u < H2D) {
            int col = gg*H2D + u;
            int kr = -1;
            if (c < H1D) kr = c;
            else if (c >= 36 && c < 36 + H2D) kr = H1D + (c - 36);
            if (kr >= 0) v = W2g[kr*120 + col];
        }
        u16 hi, lo; bsplit(v, hi, lo);
        W2h[i] = hi; W2l[i] = lo;
    }
    for (int i = tid; i < N1; i += NT) {
        int u = i >> 2, gg = i & 3;
        b1s[i] = (u < H1D) ? b1g[gg*H1D + u] : 0.f;
    }
    for (int i = tid; i < N2; i += NT) {
        int u = i >> 2, gg = i & 3;
        b2s[i] = (u < H2D) ? b2g[gg*H2D + u] : 0.f;
    }
    {
        const int tx0 = dir ? (T_STEPS - 1) : 0;
        const size_t base = ((size_t)tx0 * NBLK + bti) * 2560;
        for (int i = tid; i < 2560; i += NT) {
            int r = i / 40, d = i - r * 40;
            A1h[ABUF + r*KP + 36 + d] = g_xhi[base + i];
            A1l[ABUF + r*KP + 36 + d] = g_xlo[base + i];
        }
    }
    __syncthreads();

    const int warp = tid >> 5, lane = tid & 31;
    float cst[6] = {0.f,0.f,0.f,0.f,0.f,0.f};

    for (int tk = 0; tk <= T_STEPS; ++tk) {
        const int wb = tk & 1, rb = wb ^ 1;

        if (warp < 12) {
            if (tk < T_STEPS) {
                const int mi = warp & 3, ngp = warp >> 2;
                mma_cell<6>(A1h + rb*ABUF, A1l + rb*ABUF, W1h, W1l,
                            b1s, cst,
                            A1h + wb*ABUF, A1l + wb*ABUF,
                            A2h + wb*ABUF, A2l + wb*ABUF, 0,
                            (float*)0, mi, ngp*6, lane);
            }
        } else if (warp < 24) {
            if (tk >= 1) {
                const int w2 = warp - 12;
                const int mi = w2 & 3, ngp = w2 >> 2;
                const int tx = dir ? (T_STEPS - tk) : (tk - 1);
                float* ghb = g_hbuf + ((size_t)(tx*60 + dir*H2D))*BATCH + b0g;
                if (ngp == 0)
                    mma_cell<6>(A2h + rb*ABUF, A2l + rb*ABUF, W2h, W2l,
                                b2s, cst, (u16*)0, (u16*)0,
                                A2h + wb*ABUF, A2l + wb*ABUF, 36,
                                ghb, mi, 0, lane);
                else if (ngp == 1)
                    mma_cell<5>(A2h + rb*ABUF, A2l + rb*ABUF, W2h, W2l,
                                b2s, cst, (u16*)0, (u16*)0,
                                A2h + wb*ABUF, A2l + wb*ABUF, 36,
                                ghb, mi, 6, lane);
                else
                    mma_cell<5>(A2h + rb*ABUF, A2l + rb*ABUF, W2h, W2l,
                                b2s, cst, (u16*)0, (u16*)0,
                                A2h + wb*ABUF, A2l + wb*ABUF, 36,
                                ghb, mi, 11, lane);
            }
        } else {
            if (tk + 1 < T_STEPS) {
                const int txn = dir ? (T_STEPS - 2 - tk) : (tk + 1);
                const size_t base = ((size_t)txn * NBLK + bti) * 2560;
                u16* dh = A1h + wb*ABUF;
                u16* dl = A1l + wb*ABUF;
                for (int i = lane; i < 640; i += 32) {
                    int r = i / 10, c = i - r * 10;
                    ((ull*)(dh + r*KP + 36))[c] = ((const ull*)(g_xhi + base + r*40))[c];
                    ((ull*)(dl + r*KP + 36))[c] = ((const ull*)(g_xlo + base + r*40))[c];
                }
            }
        }
        __syncthreads();
    }
}

// =============================== FC head ===============================
#define FCT 128
#define FOFF_W1 0
#define FOFF_W2 (FOFF_W1 + 60*52)
#define FOFF_W3 (FOFF_W2 + 50*40)
#define FOFF_B1 (FOFF_W3 + 80)
#define FOFF_B2 (FOFF_B1 + 52)
#define FOFF_B3 (FOFF_B2 + 40)
#define FSM_FLOATS (FOFF_B3 + 4)

__global__ void __launch_bounds__(FCT)
fc_kernel(const float* __restrict__ Wf1, const float* __restrict__ bf1,
          const float* __restrict__ Wf2, const float* __restrict__ bf2,
          const float* __restrict__ Wf3, const float* __restrict__ bf3,
          float* __restrict__ out)
{
    extern __shared__ float fsm[];
    float* W1s = fsm + FOFF_W1;
    float* W2s = fsm + FOFF_W2;
    float* W3s = fsm + FOFF_W3;
    float* B1s = fsm + FOFF_B1;
    float* B2s = fsm + FOFF_B2;
    float* B3s = fsm + FOFF_B3;

    const int tid = threadIdx.x;

    for (int i = tid; i < 60*52; i += FCT) {
        int k = i / 52, j = i - k * 52;
        W1s[i] = (j < 50) ? Wf1[k*50 + j] : 0.f;
    }
    for (int i = tid; i < 50*40; i += FCT) W2s[i] = Wf2[i];
    for (int i = tid; i < 80;    i += FCT) W3s[i] = Wf3[i];
    for (int i = tid; i < 52;    i += FCT) B1s[i] = (i < 50) ? bf1[i] : 0.f;
    for (int i = tid; i < 40;    i += FCT) B2s[i] = bf2[i];
    for (int i = tid; i < 2;     i += FCT) B3s[i] = bf3[i];
    __syncthreads();

    const int bi = blockIdx.x & 31;
    const int t  = blockIdx.x >> 5;
    const int b0 = bi * FCT;
    const float* __restrict__ hb = &g_hbuf[(size_t)t * 60 * BATCH + b0 + tid];

    // fc1: 60 -> 50 (padded 52). R17: batched register prefetch of 12 hb values
    // per group (MLP 12) before the FMA sweep; same k-ascending accumulation
    // order as before -> bit-identical results.
    ull acc1[26];
    #pragma unroll
    for (int j = 0; j < 26; ++j) acc1[j] = pack2(B1s[2*j], B1s[2*j+1]);
    #pragma unroll
    for (int kb = 0; kb < 60; kb += 12) {
        float v[12];
        #pragma unroll
        for (int j = 0; j < 12; ++j) v[j] = hb[(size_t)(kb + j) * BATCH];
        #pragma unroll
        for (int j = 0; j < 12; ++j) {
            ull vv = pack2(v[j], v[j]);
            const float* wr = W1s + (kb + j) * 52;
            #pragma unroll
            for (int q = 0; q < 13; ++q) {
                ulonglong2 w = *(const ulonglong2*)(wr + q*4);
                acc1[2*q]   = fma2(vv, w.x, acc1[2*q]);
                acc1[2*q+1] = fma2(vv, w.y, acc1[2*q+1]);
            }
        }
    }
    float a1[52];
    #pragma unroll
    for (int j = 0; j < 26; ++j) {
        float lo, hi; unpack2(acc1[j], lo, hi);
        a1[2*j]   = fmaxf(lo, 0.f);
        a1[2*j+1] = fmaxf(hi, 0.f);
    }

    // fc2: 50 -> 40
    ull acc2[20];
    #pragma unroll
    for (int j = 0; j < 20; ++j) acc2[j] = pack2(B2s[2*j], B2s[2*j+1]);
    #pragma unroll 5
    for (int k = 0; k < 50; ++k) {
        ull vv = pack2(a1[k], a1[k]);
        #pragma unroll
        for (int j = 0; j < 10; ++j) {
            ulonglong2 w = *(const ulonglong2*)(W2s + k*40 + j*4);
            acc2[2*j]   = fma2(vv, w.x, acc2[2*j]);
            acc2[2*j+1] = fma2(vv, w.y, acc2[2*j+1]);
        }
    }
    float a2[40];
    #pragma unroll
    for (int j = 0; j < 20; ++j) {
        float lo, hi; unpack2(acc2[j], lo, hi);
        a2[2*j]   = fmaxf(lo, 0.f);
        a2[2*j+1] = fmaxf(hi, 0.f);
    }

    // out: 40 -> 2
    float o0 = B3s[0], o1 = B3s[1];
    #pragma unroll
    for (int k = 0; k < 40; ++k) {
        o0 = fmaf(a2[k], W3s[2*k + 0], o0);
        o1 = fmaf(a2[k], W3s[2*k + 1], o1);
    }
    float2 ov = make_float2(o0, o1);
    *(float2*)(&out[((size_t)(b0 + tid) * T_STEPS + t) * 2]) = ov;
}

// ============================================================================
extern "C" void kernel_launch(void* const* d_in, const int* in_sizes, int n_in,
                              void* d_out, int out_size)
{
    const float* x     = (const float*)d_in[0];
    const float* fw_W1 = (const float*)d_in[1];
    const float* fw_b1 = (const float*)d_in[2];
    const float* fw_W2 = (const float*)d_in[3];
    const float* fw_b2 = (const float*)d_in[4];
    const float* bw_W1 = (const float*)d_in[5];
    const float* bw_b1 = (const float*)d_in[6];
    const float* bw_W2 = (const float*)d_in[7];
    const float* bw_b2 = (const float*)d_in[8];
    const float* Wf1   = (const float*)d_in[9];
    const float* bf1   = (const float*)d_in[10];
    const float* Wf2   = (const float*)d_in[11];
    const float* bf2   = (const float*)d_in[12];
    const float* Wf3   = (const float*)d_in[13];
    const float* bf3   = (const float*)d_in[14];

    cudaFuncSetAttribute(lstm_kernel, cudaFuncAttributeMaxDynamicSharedMemorySize,
                         SMEM_BYTES);
    cudaFuncSetAttribute(fc_kernel, cudaFuncAttributeMaxDynamicSharedMemorySize,
                         FSM_FLOATS * (int)sizeof(float));

    xsplit_kernel<<<dim3(T_STEPS, NBLK), TT>>>(x);

    lstm_kernel<<<dim3(NBLK, 2), NT, SMEM_BYTES>>>(
        fw_W1, fw_b1, fw_W2, fw_b2, bw_W1, bw_b1, bw_W2, bw_b2);

    fc_kernel<<<32 * T_STEPS, FCT, FSM_FLOATS * sizeof(float)>>>(
        Wf1, bf1, Wf2, bf2, Wf3, bf3, (float*)d_out);
}